// round 3
// baseline (speedup 1.0000x reference)
#include <cuda_runtime.h>
#include <cuda_bf16.h>

#define D 128
#define MAXN 50000

// Scratch (allocation-free rule: __device__ globals)
__device__ float g_fj[MAXN * D];
__device__ float g_a1[MAXN];
__device__ float g_a2[MAXN];

__device__ __forceinline__ float sigmoidf_(float x) {
    return 1.0f / (1.0f + __expf(-x));
}

// ---------------------------------------------------------------------------
// GEMM + epilogue kernel.
// Block: 256 threads = (tx 0..15) x (ty 0..15). Tile: 64 rows x 128 cols.
// Each thread: 4 rows, 8 cols ({tx*4+u, 64+tx*4+u}), both matrices.
// Epilogue: bias+relu, a1/a2 row dot (shfl-reduced over 16 tx lanes),
// self-loop fused:  out = fi + sigmoid(a1+a2)*fj.  fj,a1,a2 -> global scratch.
// ---------------------------------------------------------------------------
__global__ __launch_bounds__(256, 1)
void gat_gemm_kernel(const float* __restrict__ X,
                     const float* __restrict__ W1, const float* __restrict__ b1,
                     const float* __restrict__ W2, const float* __restrict__ b2,
                     const float* __restrict__ wa1, const float* __restrict__ ba1,
                     const float* __restrict__ wa2, const float* __restrict__ ba2,
                     float* __restrict__ out, int N)
{
    extern __shared__ float smem[];
    float* feat_s = smem;                 // 64*128 floats
    float* w1t    = smem + 64 * D;        // 128*128, layout [k][c]
    float* w2t    = w1t + D * D;

    const int tid = threadIdx.x;
    const int tx  = tid & 15;
    const int ty  = tid >> 4;
    const int row0 = blockIdx.x * 64;

    // --- Load W1/W2 transposed into smem: w*t[k*D + c] = W[c*D + k] ---
    const float4* W1v = (const float4*)W1;
    const float4* W2v = (const float4*)W2;
    for (int t = tid; t < (D * D) / 4; t += 256) {
        int c  = t & 127;
        int k4 = t >> 7;               // 0..31
        float4 w = W1v[c * 32 + k4];
        w1t[(k4 * 4 + 0) * D + c] = w.x;
        w1t[(k4 * 4 + 1) * D + c] = w.y;
        w1t[(k4 * 4 + 2) * D + c] = w.z;
        w1t[(k4 * 4 + 3) * D + c] = w.w;
        float4 u = W2v[c * 32 + k4];
        w2t[(k4 * 4 + 0) * D + c] = u.x;
        w2t[(k4 * 4 + 1) * D + c] = u.y;
        w2t[(k4 * 4 + 2) * D + c] = u.z;
        w2t[(k4 * 4 + 3) * D + c] = u.w;
    }

    // --- Load feature tile (coalesced float4) ---
    const float4* Xv = (const float4*)X;
    float4* fs4 = (float4*)feat_s;
    for (int t = tid; t < (64 * D) / 4; t += 256) {
        int r  = t >> 5;               // 0..63
        int k4 = t & 31;
        int row = row0 + r;
        float4 v = (row < N) ? Xv[(size_t)row * 32 + k4] : make_float4(0.f, 0.f, 0.f, 0.f);
        fs4[r * 32 + k4] = v;
    }
    __syncthreads();

    float acc1[4][8], acc2[4][8];
#pragma unroll
    for (int v = 0; v < 4; ++v)
#pragma unroll
        for (int u = 0; u < 8; ++u) { acc1[v][u] = 0.f; acc2[v][u] = 0.f; }

#pragma unroll 4
    for (int k = 0; k < D; ++k) {
        float4 w1a = *(const float4*)&w1t[k * D + tx * 4];
        float4 w1b = *(const float4*)&w1t[k * D + 64 + tx * 4];
        float4 w2a = *(const float4*)&w2t[k * D + tx * 4];
        float4 w2b = *(const float4*)&w2t[k * D + 64 + tx * 4];
#pragma unroll
        for (int v = 0; v < 4; ++v) {
            float f = feat_s[(ty * 4 + v) * D + k];
            acc1[v][0] = fmaf(f, w1a.x, acc1[v][0]);
            acc1[v][1] = fmaf(f, w1a.y, acc1[v][1]);
            acc1[v][2] = fmaf(f, w1a.z, acc1[v][2]);
            acc1[v][3] = fmaf(f, w1a.w, acc1[v][3]);
            acc1[v][4] = fmaf(f, w1b.x, acc1[v][4]);
            acc1[v][5] = fmaf(f, w1b.y, acc1[v][5]);
            acc1[v][6] = fmaf(f, w1b.z, acc1[v][6]);
            acc1[v][7] = fmaf(f, w1b.w, acc1[v][7]);
            acc2[v][0] = fmaf(f, w2a.x, acc2[v][0]);
            acc2[v][1] = fmaf(f, w2a.y, acc2[v][1]);
            acc2[v][2] = fmaf(f, w2a.z, acc2[v][2]);
            acc2[v][3] = fmaf(f, w2a.w, acc2[v][3]);
            acc2[v][4] = fmaf(f, w2b.x, acc2[v][4]);
            acc2[v][5] = fmaf(f, w2b.y, acc2[v][5]);
            acc2[v][6] = fmaf(f, w2b.z, acc2[v][6]);
            acc2[v][7] = fmaf(f, w2b.w, acc2[v][7]);
        }
    }

    // --- Epilogue: bias + relu, attention dots ---
    float bb1[8], bb2[8], va1[8], va2[8];
#pragma unroll
    for (int u = 0; u < 8; ++u) {
        int c = (u < 4) ? (tx * 4 + u) : (64 + tx * 4 + (u - 4));
        bb1[u] = b1[c];
        bb2[u] = b2[c];
        va1[u] = wa1[c];
        va2[u] = wa2[c];
    }
    float p1[4] = {0.f, 0.f, 0.f, 0.f};
    float p2[4] = {0.f, 0.f, 0.f, 0.f};
#pragma unroll
    for (int v = 0; v < 4; ++v) {
#pragma unroll
        for (int u = 0; u < 8; ++u) {
            float fi = fmaxf(acc1[v][u] + bb1[u], 0.f);
            float fj = fmaxf(acc2[v][u] + bb2[u], 0.f);
            acc1[v][u] = fi;
            acc2[v][u] = fj;
            p1[v] = fmaf(fi, va1[u], p1[v]);
            p2[v] = fmaf(fj, va2[u], p2[v]);
        }
    }
    // Reduce p1/p2 across the 16 tx lanes.
#pragma unroll
    for (int off = 8; off >= 1; off >>= 1) {
#pragma unroll
        for (int v = 0; v < 4; ++v) {
            p1[v] += __shfl_xor_sync(0xffffffffu, p1[v], off, 16);
            p2[v] += __shfl_xor_sync(0xffffffffu, p2[v], off, 16);
        }
    }
    const float bba1 = ba1[0];
    const float bba2 = ba2[0];

#pragma unroll
    for (int v = 0; v < 4; ++v) {
        int row = row0 + ty * 4 + v;
        if (row >= N) continue;
        float a1v = p1[v] + bba1;
        float a2v = p2[v] + bba2;
        if (tx == 0) { g_a1[row] = a1v; g_a2[row] = a2v; }
        float att = sigmoidf_(a1v + a2v);   // self-loop attention

        float4 o1 = make_float4(fmaf(att, acc2[v][0], acc1[v][0]),
                                fmaf(att, acc2[v][1], acc1[v][1]),
                                fmaf(att, acc2[v][2], acc1[v][2]),
                                fmaf(att, acc2[v][3], acc1[v][3]));
        float4 o2 = make_float4(fmaf(att, acc2[v][4], acc1[v][4]),
                                fmaf(att, acc2[v][5], acc1[v][5]),
                                fmaf(att, acc2[v][6], acc1[v][6]),
                                fmaf(att, acc2[v][7], acc1[v][7]));
        *(float4*)&out[(size_t)row * D + tx * 4]      = o1;
        *(float4*)&out[(size_t)row * D + 64 + tx * 4] = o2;

        float4 j1 = make_float4(acc2[v][0], acc2[v][1], acc2[v][2], acc2[v][3]);
        float4 j2 = make_float4(acc2[v][4], acc2[v][5], acc2[v][6], acc2[v][7]);
        *(float4*)&g_fj[(size_t)row * D + tx * 4]      = j1;
        *(float4*)&g_fj[(size_t)row * D + 64 + tx * 4] = j2;
    }
}

// ---------------------------------------------------------------------------
// Edge scatter: one warp per edge.  edge_index is INT32 (JAX x64 disabled
// silently downcasts the requested int64 -> int32).
// out[i][:] += sigmoid(a1[i] + a2[j]) * fj[j][:]  via 4x scalar atomicAdd.
// ---------------------------------------------------------------------------
__global__ __launch_bounds__(256)
void gat_scatter_kernel(const int* __restrict__ ei,
                        float* __restrict__ out, int E, int N)
{
    int w = (int)((blockIdx.x * blockDim.x + threadIdx.x) >> 5);
    if (w >= E) return;
    int lane = threadIdx.x & 31;

    int i = ei[w];       // edge_index[0][e] : destination (segment id)
    int j = ei[E + w];   // edge_index[1][e] : source

    // Guard: if dtype inference is wrong these go wild -> skip instead of trap.
    if ((unsigned)i >= (unsigned)N || (unsigned)j >= (unsigned)N) return;

    float att = sigmoidf_(g_a1[i] + g_a2[j]);

    float4 v = *(const float4*)&g_fj[(size_t)j * D + lane * 4];
    float* dst = &out[(size_t)i * D + lane * 4];
    atomicAdd(dst + 0, att * v.x);
    atomicAdd(dst + 1, att * v.y);
    atomicAdd(dst + 2, att * v.z);
    atomicAdd(dst + 3, att * v.w);
}

// ---------------------------------------------------------------------------
extern "C" void kernel_launch(void* const* d_in, const int* in_sizes, int n_in,
                              void* d_out, int out_size)
{
    const float* X   = (const float*)d_in[0];
    const float* W1  = (const float*)d_in[1];
    const float* b1  = (const float*)d_in[2];
    const float* W2  = (const float*)d_in[3];
    const float* b2  = (const float*)d_in[4];
    const float* wa1 = (const float*)d_in[5];
    const float* ba1 = (const float*)d_in[6];
    const float* wa2 = (const float*)d_in[7];
    const float* ba2 = (const float*)d_in[8];
    const int*   ei  = (const int*)d_in[9];   // int32 edge_index [2, E]
    float* out = (float*)d_out;

    int N = in_sizes[0] / D;
    int E = in_sizes[9] / 2;

    const int smem_bytes = (64 * D + 2 * D * D) * (int)sizeof(float);  // 160 KB
    cudaFuncSetAttribute(gat_gemm_kernel,
                         cudaFuncAttributeMaxDynamicSharedMemorySize, smem_bytes);

    int gemm_blocks = (N + 63) / 64;
    gat_gemm_kernel<<<gemm_blocks, 256, smem_bytes>>>(
        X, W1, b1, W2, b2, wa1, ba1, wa2, ba2, out, N);

    int scat_blocks = (E + 7) / 8;   // 8 warps (edges) per 256-thread block
    gat_scatter_kernel<<<scat_blocks, 256>>>(ei, out, E, N);
}

// round 4
// speedup vs baseline: 1.2771x; 1.2771x over previous
#include <cuda_runtime.h>
#include <cuda_bf16.h>

#define D 128
#define MAXN 50000
#define MAXE 800000

// Scratch (allocation-free rule: __device__ globals)
__device__ float g_fj[MAXN * D];
__device__ float g_a1[MAXN];
__device__ float g_a2[MAXN];
__device__ int   g_cnt[MAXN];
__device__ int   g_rowptr[MAXN + 1];
__device__ int   g_cursor[MAXN];
__device__ int   g_col[MAXE];
__device__ float g_attw[MAXE];

__device__ __forceinline__ float sigmoidf_(float x) {
    return 1.0f / (1.0f + __expf(-x));
}

// ---------------------------------------------------------------------------
// GEMM + epilogue (unchanged from R3): computes fi,fj,a1,a2 and writes
// out = fi + sigmoid(a1+a2)*fj  (self-loop fused).
// ---------------------------------------------------------------------------
__global__ __launch_bounds__(256, 1)
void gat_gemm_kernel(const float* __restrict__ X,
                     const float* __restrict__ W1, const float* __restrict__ b1,
                     const float* __restrict__ W2, const float* __restrict__ b2,
                     const float* __restrict__ wa1, const float* __restrict__ ba1,
                     const float* __restrict__ wa2, const float* __restrict__ ba2,
                     float* __restrict__ out, int N)
{
    extern __shared__ float smem[];
    float* feat_s = smem;                 // 64*128
    float* w1t    = smem + 64 * D;        // 128*128 [k][c]
    float* w2t    = w1t + D * D;

    const int tid = threadIdx.x;
    const int tx  = tid & 15;
    const int ty  = tid >> 4;
    const int row0 = blockIdx.x * 64;

    const float4* W1v = (const float4*)W1;
    const float4* W2v = (const float4*)W2;
    for (int t = tid; t < (D * D) / 4; t += 256) {
        int c  = t & 127;
        int k4 = t >> 7;
        float4 w = W1v[c * 32 + k4];
        w1t[(k4 * 4 + 0) * D + c] = w.x;
        w1t[(k4 * 4 + 1) * D + c] = w.y;
        w1t[(k4 * 4 + 2) * D + c] = w.z;
        w1t[(k4 * 4 + 3) * D + c] = w.w;
        float4 u = W2v[c * 32 + k4];
        w2t[(k4 * 4 + 0) * D + c] = u.x;
        w2t[(k4 * 4 + 1) * D + c] = u.y;
        w2t[(k4 * 4 + 2) * D + c] = u.z;
        w2t[(k4 * 4 + 3) * D + c] = u.w;
    }

    const float4* Xv = (const float4*)X;
    float4* fs4 = (float4*)feat_s;
    for (int t = tid; t < (64 * D) / 4; t += 256) {
        int r  = t >> 5;
        int k4 = t & 31;
        int row = row0 + r;
        float4 v = (row < N) ? Xv[(size_t)row * 32 + k4] : make_float4(0.f, 0.f, 0.f, 0.f);
        fs4[r * 32 + k4] = v;
    }
    __syncthreads();

    float acc1[4][8], acc2[4][8];
#pragma unroll
    for (int v = 0; v < 4; ++v)
#pragma unroll
        for (int u = 0; u < 8; ++u) { acc1[v][u] = 0.f; acc2[v][u] = 0.f; }

#pragma unroll 4
    for (int k = 0; k < D; ++k) {
        float4 w1a = *(const float4*)&w1t[k * D + tx * 4];
        float4 w1b = *(const float4*)&w1t[k * D + 64 + tx * 4];
        float4 w2a = *(const float4*)&w2t[k * D + tx * 4];
        float4 w2b = *(const float4*)&w2t[k * D + 64 + tx * 4];
#pragma unroll
        for (int v = 0; v < 4; ++v) {
            float f = feat_s[(ty * 4 + v) * D + k];
            acc1[v][0] = fmaf(f, w1a.x, acc1[v][0]);
            acc1[v][1] = fmaf(f, w1a.y, acc1[v][1]);
            acc1[v][2] = fmaf(f, w1a.z, acc1[v][2]);
            acc1[v][3] = fmaf(f, w1a.w, acc1[v][3]);
            acc1[v][4] = fmaf(f, w1b.x, acc1[v][4]);
            acc1[v][5] = fmaf(f, w1b.y, acc1[v][5]);
            acc1[v][6] = fmaf(f, w1b.z, acc1[v][6]);
            acc1[v][7] = fmaf(f, w1b.w, acc1[v][7]);
            acc2[v][0] = fmaf(f, w2a.x, acc2[v][0]);
            acc2[v][1] = fmaf(f, w2a.y, acc2[v][1]);
            acc2[v][2] = fmaf(f, w2a.z, acc2[v][2]);
            acc2[v][3] = fmaf(f, w2a.w, acc2[v][3]);
            acc2[v][4] = fmaf(f, w2b.x, acc2[v][4]);
            acc2[v][5] = fmaf(f, w2b.y, acc2[v][5]);
            acc2[v][6] = fmaf(f, w2b.z, acc2[v][6]);
            acc2[v][7] = fmaf(f, w2b.w, acc2[v][7]);
        }
    }

    float bb1[8], bb2[8], va1[8], va2[8];
#pragma unroll
    for (int u = 0; u < 8; ++u) {
        int c = (u < 4) ? (tx * 4 + u) : (64 + tx * 4 + (u - 4));
        bb1[u] = b1[c];
        bb2[u] = b2[c];
        va1[u] = wa1[c];
        va2[u] = wa2[c];
    }
    float p1[4] = {0.f, 0.f, 0.f, 0.f};
    float p2[4] = {0.f, 0.f, 0.f, 0.f};
#pragma unroll
    for (int v = 0; v < 4; ++v) {
#pragma unroll
        for (int u = 0; u < 8; ++u) {
            float fi = fmaxf(acc1[v][u] + bb1[u], 0.f);
            float fj = fmaxf(acc2[v][u] + bb2[u], 0.f);
            acc1[v][u] = fi;
            acc2[v][u] = fj;
            p1[v] = fmaf(fi, va1[u], p1[v]);
            p2[v] = fmaf(fj, va2[u], p2[v]);
        }
    }
#pragma unroll
    for (int off = 8; off >= 1; off >>= 1) {
#pragma unroll
        for (int v = 0; v < 4; ++v) {
            p1[v] += __shfl_xor_sync(0xffffffffu, p1[v], off, 16);
            p2[v] += __shfl_xor_sync(0xffffffffu, p2[v], off, 16);
        }
    }
    const float bba1 = ba1[0];
    const float bba2 = ba2[0];

#pragma unroll
    for (int v = 0; v < 4; ++v) {
        int row = row0 + ty * 4 + v;
        if (row >= N) continue;
        float a1v = p1[v] + bba1;
        float a2v = p2[v] + bba2;
        if (tx == 0) { g_a1[row] = a1v; g_a2[row] = a2v; }
        float att = sigmoidf_(a1v + a2v);

        float4 o1 = make_float4(fmaf(att, acc2[v][0], acc1[v][0]),
                                fmaf(att, acc2[v][1], acc1[v][1]),
                                fmaf(att, acc2[v][2], acc1[v][2]),
                                fmaf(att, acc2[v][3], acc1[v][3]));
        float4 o2 = make_float4(fmaf(att, acc2[v][4], acc1[v][4]),
                                fmaf(att, acc2[v][5], acc1[v][5]),
                                fmaf(att, acc2[v][6], acc1[v][6]),
                                fmaf(att, acc2[v][7], acc1[v][7]));
        *(float4*)&out[(size_t)row * D + tx * 4]      = o1;
        *(float4*)&out[(size_t)row * D + 64 + tx * 4] = o2;

        float4 j1 = make_float4(acc2[v][0], acc2[v][1], acc2[v][2], acc2[v][3]);
        float4 j2 = make_float4(acc2[v][4], acc2[v][5], acc2[v][6], acc2[v][7]);
        *(float4*)&g_fj[(size_t)row * D + tx * 4]      = j1;
        *(float4*)&g_fj[(size_t)row * D + 64 + tx * 4] = j2;
    }
}

// ---------------------------------------------------------------------------
// CSR build
// ---------------------------------------------------------------------------
__global__ void zero_cnt_kernel(int N) {
    int t = blockIdx.x * blockDim.x + threadIdx.x;
    if (t < N) g_cnt[t] = 0;
}

__global__ void hist_kernel(const int* __restrict__ ei, int E, int N) {
    int e = blockIdx.x * blockDim.x + threadIdx.x;
    if (e >= E) return;
    int i = ei[e];
    if ((unsigned)i < (unsigned)N) atomicAdd(&g_cnt[i], 1);
}

// Single-block exclusive scan: row_ptr + cursor. 1024 threads, chunked.
__global__ __launch_bounds__(1024)
void scan_kernel(int N) {
    __shared__ int partial[1024];
    const int t = threadIdx.x;
    const int chunk = (N + 1023) / 1024;
    const int start = t * chunk;
    const int end   = min(start + chunk, N);

    int s = 0;
    for (int e = start; e < end; ++e) s += g_cnt[e];
    partial[t] = s;
    __syncthreads();

    // Hillis-Steele inclusive scan
    for (int off = 1; off < 1024; off <<= 1) {
        int v = (t >= off) ? partial[t - off] : 0;
        __syncthreads();
        partial[t] += v;
        __syncthreads();
    }

    int run = partial[t] - s;   // exclusive prefix of this chunk
    for (int e = start; e < end; ++e) {
        g_rowptr[e] = run;
        g_cursor[e] = run;
        run += g_cnt[e];
    }
    if (t == 1023) g_rowptr[N] = partial[1023];
}

// Fill CSR: col + precomputed attention weight (a1/a2 from GEMM ready).
__global__ void fill_kernel(const int* __restrict__ ei, int E, int N) {
    int e = blockIdx.x * blockDim.x + threadIdx.x;
    if (e >= E) return;
    int i = ei[e];
    int j = ei[E + e];
    if ((unsigned)i >= (unsigned)N || (unsigned)j >= (unsigned)N) return;
    int pos = atomicAdd(&g_cursor[i], 1);
    g_col[pos]  = j;
    g_attw[pos] = sigmoidf_(g_a1[i] + g_a2[j]);
}

// ---------------------------------------------------------------------------
// Gather: one warp per destination node. No output atomics.
// ---------------------------------------------------------------------------
__global__ __launch_bounds__(256)
void gat_gather_kernel(float* __restrict__ out, int N) {
    int w = (int)((blockIdx.x * blockDim.x + threadIdx.x) >> 5);
    if (w >= N) return;
    int lane = threadIdx.x & 31;

    int beg = g_rowptr[w];
    int endp = g_rowptr[w + 1];
    if (beg == endp) return;

    const float4* fj4 = (const float4*)g_fj;
    float4 acc = make_float4(0.f, 0.f, 0.f, 0.f);

    for (int base = beg; base < endp; base += 32) {
        int idx = base + lane;
        int j = 0;
        float att = 0.f;
        if (idx < endp) { j = g_col[idx]; att = g_attw[idx]; }
        int cnt = min(32, endp - base);
        for (int k = 0; k < cnt; ++k) {
            int   jj = __shfl_sync(0xffffffffu, j, k);
            float aa = __shfl_sync(0xffffffffu, att, k);
            float4 v = fj4[(size_t)jj * 32 + lane];
            acc.x = fmaf(aa, v.x, acc.x);
            acc.y = fmaf(aa, v.y, acc.y);
            acc.z = fmaf(aa, v.z, acc.z);
            acc.w = fmaf(aa, v.w, acc.w);
        }
    }

    float4* o = (float4*)&out[(size_t)w * D + lane * 4];
    float4 cur = *o;
    cur.x += acc.x; cur.y += acc.y; cur.z += acc.z; cur.w += acc.w;
    *o = cur;
}

// ---------------------------------------------------------------------------
extern "C" void kernel_launch(void* const* d_in, const int* in_sizes, int n_in,
                              void* d_out, int out_size)
{
    const float* X   = (const float*)d_in[0];
    const float* W1  = (const float*)d_in[1];
    const float* b1  = (const float*)d_in[2];
    const float* W2  = (const float*)d_in[3];
    const float* b2  = (const float*)d_in[4];
    const float* wa1 = (const float*)d_in[5];
    const float* ba1 = (const float*)d_in[6];
    const float* wa2 = (const float*)d_in[7];
    const float* ba2 = (const float*)d_in[8];
    const int*   ei  = (const int*)d_in[9];   // int32 edge_index [2, E]
    float* out = (float*)d_out;

    int N = in_sizes[0] / D;
    int E = in_sizes[9] / 2;

    const int smem_bytes = (64 * D + 2 * D * D) * (int)sizeof(float);  // 160 KB
    cudaFuncSetAttribute(gat_gemm_kernel,
                         cudaFuncAttributeMaxDynamicSharedMemorySize, smem_bytes);

    // 1) GEMM (produces fi->out with self-loop, fj/a1/a2 scratch)
    gat_gemm_kernel<<<(N + 63) / 64, 256, smem_bytes>>>(
        X, W1, b1, W2, b2, wa1, ba1, wa2, ba2, out, N);

    // 2) CSR build
    zero_cnt_kernel<<<(N + 255) / 256, 256>>>(N);
    hist_kernel<<<(E + 255) / 256, 256>>>(ei, E, N);
    scan_kernel<<<1, 1024>>>(N);
    fill_kernel<<<(E + 255) / 256, 256>>>(ei, E, N);

    // 3) Gather (one warp per node, no atomics)
    gat_gather_kernel<<<(N * 32 + 255) / 256, 256>>>(out, N);
}

// round 5
// speedup vs baseline: 1.6348x; 1.2800x over previous
#include <cuda_runtime.h>
#include <cuda_bf16.h>

#define D 128
#define MAXN 50000
#define MAXE 800000

// Scratch (allocation-free rule: __device__ globals)
__device__ float g_fj[MAXN * D];
__device__ float g_a1[MAXN];
__device__ float g_a2[MAXN];
__device__ int   g_cnt[MAXN];
__device__ int   g_rowptr[MAXN + 1];
__device__ int   g_cursor[MAXN];
__device__ int   g_col[MAXE];
__device__ float g_attw[MAXE];

__device__ __forceinline__ float sigmoidf_(float x) {
    return 1.0f / (1.0f + __expf(-x));
}

// ---------------------------------------------------------------------------
// GEMM + epilogue: computes fi,fj,a1,a2; writes out = fi + sigmoid(a1+a2)*fj.
// ---------------------------------------------------------------------------
__global__ __launch_bounds__(256, 1)
void gat_gemm_kernel(const float* __restrict__ X,
                     const float* __restrict__ W1, const float* __restrict__ b1,
                     const float* __restrict__ W2, const float* __restrict__ b2,
                     const float* __restrict__ wa1, const float* __restrict__ ba1,
                     const float* __restrict__ wa2, const float* __restrict__ ba2,
                     float* __restrict__ out, int N)
{
    extern __shared__ float smem[];
    float* feat_s = smem;                 // 64*128
    float* w1t    = smem + 64 * D;        // 128*128 [k][c]
    float* w2t    = w1t + D * D;

    const int tid = threadIdx.x;
    const int tx  = tid & 15;
    const int ty  = tid >> 4;
    const int row0 = blockIdx.x * 64;

    const float4* W1v = (const float4*)W1;
    const float4* W2v = (const float4*)W2;
    for (int t = tid; t < (D * D) / 4; t += 256) {
        int c  = t & 127;
        int k4 = t >> 7;
        float4 w = W1v[c * 32 + k4];
        w1t[(k4 * 4 + 0) * D + c] = w.x;
        w1t[(k4 * 4 + 1) * D + c] = w.y;
        w1t[(k4 * 4 + 2) * D + c] = w.z;
        w1t[(k4 * 4 + 3) * D + c] = w.w;
        float4 u = W2v[c * 32 + k4];
        w2t[(k4 * 4 + 0) * D + c] = u.x;
        w2t[(k4 * 4 + 1) * D + c] = u.y;
        w2t[(k4 * 4 + 2) * D + c] = u.z;
        w2t[(k4 * 4 + 3) * D + c] = u.w;
    }

    const float4* Xv = (const float4*)X;
    float4* fs4 = (float4*)feat_s;
    for (int t = tid; t < (64 * D) / 4; t += 256) {
        int r  = t >> 5;
        int k4 = t & 31;
        int row = row0 + r;
        float4 v = (row < N) ? Xv[(size_t)row * 32 + k4] : make_float4(0.f, 0.f, 0.f, 0.f);
        fs4[r * 32 + k4] = v;
    }
    __syncthreads();

    float acc1[4][8], acc2[4][8];
#pragma unroll
    for (int v = 0; v < 4; ++v)
#pragma unroll
        for (int u = 0; u < 8; ++u) { acc1[v][u] = 0.f; acc2[v][u] = 0.f; }

#pragma unroll 4
    for (int k = 0; k < D; ++k) {
        float4 w1a = *(const float4*)&w1t[k * D + tx * 4];
        float4 w1b = *(const float4*)&w1t[k * D + 64 + tx * 4];
        float4 w2a = *(const float4*)&w2t[k * D + tx * 4];
        float4 w2b = *(const float4*)&w2t[k * D + 64 + tx * 4];
#pragma unroll
        for (int v = 0; v < 4; ++v) {
            float f = feat_s[(ty * 4 + v) * D + k];
            acc1[v][0] = fmaf(f, w1a.x, acc1[v][0]);
            acc1[v][1] = fmaf(f, w1a.y, acc1[v][1]);
            acc1[v][2] = fmaf(f, w1a.z, acc1[v][2]);
            acc1[v][3] = fmaf(f, w1a.w, acc1[v][3]);
            acc1[v][4] = fmaf(f, w1b.x, acc1[v][4]);
            acc1[v][5] = fmaf(f, w1b.y, acc1[v][5]);
            acc1[v][6] = fmaf(f, w1b.z, acc1[v][6]);
            acc1[v][7] = fmaf(f, w1b.w, acc1[v][7]);
            acc2[v][0] = fmaf(f, w2a.x, acc2[v][0]);
            acc2[v][1] = fmaf(f, w2a.y, acc2[v][1]);
            acc2[v][2] = fmaf(f, w2a.z, acc2[v][2]);
            acc2[v][3] = fmaf(f, w2a.w, acc2[v][3]);
            acc2[v][4] = fmaf(f, w2b.x, acc2[v][4]);
            acc2[v][5] = fmaf(f, w2b.y, acc2[v][5]);
            acc2[v][6] = fmaf(f, w2b.z, acc2[v][6]);
            acc2[v][7] = fmaf(f, w2b.w, acc2[v][7]);
        }
    }

    float bb1[8], bb2[8], va1[8], va2[8];
#pragma unroll
    for (int u = 0; u < 8; ++u) {
        int c = (u < 4) ? (tx * 4 + u) : (64 + tx * 4 + (u - 4));
        bb1[u] = b1[c];
        bb2[u] = b2[c];
        va1[u] = wa1[c];
        va2[u] = wa2[c];
    }
    float p1[4] = {0.f, 0.f, 0.f, 0.f};
    float p2[4] = {0.f, 0.f, 0.f, 0.f};
#pragma unroll
    for (int v = 0; v < 4; ++v) {
#pragma unroll
        for (int u = 0; u < 8; ++u) {
            float fi = fmaxf(acc1[v][u] + bb1[u], 0.f);
            float fj = fmaxf(acc2[v][u] + bb2[u], 0.f);
            acc1[v][u] = fi;
            acc2[v][u] = fj;
            p1[v] = fmaf(fi, va1[u], p1[v]);
            p2[v] = fmaf(fj, va2[u], p2[v]);
        }
    }
#pragma unroll
    for (int off = 8; off >= 1; off >>= 1) {
#pragma unroll
        for (int v = 0; v < 4; ++v) {
            p1[v] += __shfl_xor_sync(0xffffffffu, p1[v], off, 16);
            p2[v] += __shfl_xor_sync(0xffffffffu, p2[v], off, 16);
        }
    }
    const float bba1 = ba1[0];
    const float bba2 = ba2[0];

#pragma unroll
    for (int v = 0; v < 4; ++v) {
        int row = row0 + ty * 4 + v;
        if (row >= N) continue;
        float a1v = p1[v] + bba1;
        float a2v = p2[v] + bba2;
        if (tx == 0) { g_a1[row] = a1v; g_a2[row] = a2v; }
        float att = sigmoidf_(a1v + a2v);

        float4 o1 = make_float4(fmaf(att, acc2[v][0], acc1[v][0]),
                                fmaf(att, acc2[v][1], acc1[v][1]),
                                fmaf(att, acc2[v][2], acc1[v][2]),
                                fmaf(att, acc2[v][3], acc1[v][3]));
        float4 o2 = make_float4(fmaf(att, acc2[v][4], acc1[v][4]),
                                fmaf(att, acc2[v][5], acc1[v][5]),
                                fmaf(att, acc2[v][6], acc1[v][6]),
                                fmaf(att, acc2[v][7], acc1[v][7]));
        *(float4*)&out[(size_t)row * D + tx * 4]      = o1;
        *(float4*)&out[(size_t)row * D + 64 + tx * 4] = o2;

        float4 j1 = make_float4(acc2[v][0], acc2[v][1], acc2[v][2], acc2[v][3]);
        float4 j2 = make_float4(acc2[v][4], acc2[v][5], acc2[v][6], acc2[v][7]);
        *(float4*)&g_fj[(size_t)row * D + tx * 4]      = j1;
        *(float4*)&g_fj[(size_t)row * D + 64 + tx * 4] = j2;
    }
}

// ---------------------------------------------------------------------------
// CSR build
// ---------------------------------------------------------------------------
__global__ void zero_cnt_kernel(int N) {
    int t = blockIdx.x * blockDim.x + threadIdx.x;
    if (t < N) g_cnt[t] = 0;
}

__global__ void hist_kernel(const int* __restrict__ ei, int E, int N) {
    int e = blockIdx.x * blockDim.x + threadIdx.x;
    if (e >= E) return;
    int i = ei[e];
    if ((unsigned)i < (unsigned)N) atomicAdd(&g_cnt[i], 1);
}

// Single-block exclusive scan, fully smem-staged.
// All global accesses coalesced (grid-stride); chunk work in smem.
// Lane stride during chunk phases = chunk(=49) ints; 49 mod 32 = 17 coprime
// with 32 -> bank-conflict-free.
__global__ __launch_bounds__(1024)
void scan_kernel(int N) {
    extern __shared__ int s[];            // [MAXN] counts/prefix + [1024] partials
    int* partial = s + MAXN;
    const int t = threadIdx.x;

    // Coalesced load of counts into smem.
    for (int i = t; i < N; i += 1024) s[i] = g_cnt[i];
    __syncthreads();

    // Per-thread chunk: exclusive scan in place, keep chunk sum.
    const int chunk = (N + 1023) / 1024;
    const int start = t * chunk;
    const int end   = min(start + chunk, N);
    int sum = 0;
    for (int i = start; i < end; ++i) { int c = s[i]; s[i] = sum; sum += c; }
    partial[t] = sum;
    __syncthreads();

    // Hillis-Steele inclusive scan of 1024 partials.
    for (int off = 1; off < 1024; off <<= 1) {
        int v = (t >= off) ? partial[t - off] : 0;
        __syncthreads();
        partial[t] += v;
        __syncthreads();
    }

    // Add exclusive chunk offset back into smem.
    int offs = partial[t] - sum;
    for (int i = start; i < end; ++i) s[i] += offs;
    __syncthreads();

    // Coalesced store of rowptr + cursor.
    for (int i = t; i < N; i += 1024) {
        int r = s[i];
        g_rowptr[i] = r;
        g_cursor[i] = r;
    }
    if (t == 1023) g_rowptr[N] = partial[1023];
}

// Fill CSR: col + precomputed attention weight (a1/a2 from GEMM ready).
__global__ void fill_kernel(const int* __restrict__ ei, int E, int N) {
    int e = blockIdx.x * blockDim.x + threadIdx.x;
    if (e >= E) return;
    int i = ei[e];
    int j = ei[E + e];
    if ((unsigned)i >= (unsigned)N || (unsigned)j >= (unsigned)N) return;
    int pos = atomicAdd(&g_cursor[i], 1);
    g_col[pos]  = j;
    g_attw[pos] = sigmoidf_(g_a1[i] + g_a2[j]);
}

// ---------------------------------------------------------------------------
// Gather: one warp per destination node. No output atomics.
// ---------------------------------------------------------------------------
__global__ __launch_bounds__(256)
void gat_gather_kernel(float* __restrict__ out, int N) {
    int w = (int)((blockIdx.x * blockDim.x + threadIdx.x) >> 5);
    if (w >= N) return;
    int lane = threadIdx.x & 31;

    int beg = g_rowptr[w];
    int endp = g_rowptr[w + 1];
    if (beg == endp) return;

    const float4* fj4 = (const float4*)g_fj;
    float4 acc = make_float4(0.f, 0.f, 0.f, 0.f);

    for (int base = beg; base < endp; base += 32) {
        int idx = base + lane;
        int j = 0;
        float att = 0.f;
        if (idx < endp) { j = g_col[idx]; att = g_attw[idx]; }
        int cnt = min(32, endp - base);
        for (int k = 0; k < cnt; ++k) {
            int   jj = __shfl_sync(0xffffffffu, j, k);
            float aa = __shfl_sync(0xffffffffu, att, k);
            float4 v = fj4[(size_t)jj * 32 + lane];
            acc.x = fmaf(aa, v.x, acc.x);
            acc.y = fmaf(aa, v.y, acc.y);
            acc.z = fmaf(aa, v.z, acc.z);
            acc.w = fmaf(aa, v.w, acc.w);
        }
    }

    float4* o = (float4*)&out[(size_t)w * D + lane * 4];
    float4 cur = *o;
    cur.x += acc.x; cur.y += acc.y; cur.z += acc.z; cur.w += acc.w;
    *o = cur;
}

// ---------------------------------------------------------------------------
extern "C" void kernel_launch(void* const* d_in, const int* in_sizes, int n_in,
                              void* d_out, int out_size)
{
    const float* X   = (const float*)d_in[0];
    const float* W1  = (const float*)d_in[1];
    const float* b1  = (const float*)d_in[2];
    const float* W2  = (const float*)d_in[3];
    const float* b2  = (const float*)d_in[4];
    const float* wa1 = (const float*)d_in[5];
    const float* ba1 = (const float*)d_in[6];
    const float* wa2 = (const float*)d_in[7];
    const float* ba2 = (const float*)d_in[8];
    const int*   ei  = (const int*)d_in[9];   // int32 edge_index [2, E]
    float* out = (float*)d_out;

    int N = in_sizes[0] / D;
    int E = in_sizes[9] / 2;

    const int gemm_smem = (64 * D + 2 * D * D) * (int)sizeof(float);   // 160 KB
    cudaFuncSetAttribute(gat_gemm_kernel,
                         cudaFuncAttributeMaxDynamicSharedMemorySize, gemm_smem);
    const int scan_smem = (MAXN + 1024) * (int)sizeof(int);            // ~204 KB
    cudaFuncSetAttribute(scan_kernel,
                         cudaFuncAttributeMaxDynamicSharedMemorySize, scan_smem);

    // 1) GEMM (produces fi->out with self-loop, fj/a1/a2 scratch)
    gat_gemm_kernel<<<(N + 63) / 64, 256, gemm_smem>>>(
        X, W1, b1, W2, b2, wa1, ba1, wa2, ba2, out, N);

    // 2) CSR build
    zero_cnt_kernel<<<(N + 255) / 256, 256>>>(N);
    hist_kernel<<<(E + 255) / 256, 256>>>(ei, E, N);
    scan_kernel<<<1, 1024, scan_smem>>>(N);
    fill_kernel<<<(E + 255) / 256, 256>>>(ei, E, N);

    // 3) Gather (one warp per node, no atomics)
    gat_gather_kernel<<<(N * 32 + 255) / 256, 256>>>(out, N);
}

// round 6
// speedup vs baseline: 2.4202x; 1.4804x over previous
#include <cuda_runtime.h>
#include <cuda_bf16.h>
#include <cstdint>

#define D 128
#define MAXN 50000
#define MAXE 800000

// Scratch (allocation-free rule: __device__ globals)
__device__ float g_fj[MAXN * D];
__device__ float g_a1[MAXN];
__device__ float g_a2[MAXN];
__device__ int   g_cnt[MAXN];
__device__ int   g_rowptr[MAXN + 1];
__device__ int   g_cursor[MAXN];
__device__ int   g_col[MAXE];
__device__ float g_attw[MAXE];

__device__ __forceinline__ float sigmoidf_(float x) {
    return 1.0f / (1.0f + __expf(-x));
}

__device__ __forceinline__ uint32_t f2tf32(float x) {
    uint32_t r;
    asm("cvt.rna.tf32.f32 %0, %1;" : "=r"(r) : "f"(x));
    return r;
}

__device__ __forceinline__ void mma_tf32(float& d0, float& d1, float& d2, float& d3,
                                         uint32_t a0, uint32_t a1, uint32_t a2, uint32_t a3,
                                         uint32_t b0, uint32_t b1) {
    asm volatile("mma.sync.aligned.m16n8k8.row.col.f32.tf32.tf32.f32 "
                 "{%0,%1,%2,%3},{%4,%5,%6,%7},{%8,%9},{%0,%1,%2,%3};"
                 : "+f"(d0), "+f"(d1), "+f"(d2), "+f"(d3)
                 : "r"(a0), "r"(a1), "r"(a2), "r"(a3), "r"(b0), "r"(b1));
}

// ---------------------------------------------------------------------------
// tf32 tensor-core GEMM + epilogue.
// Block: 512 threads (16 warps). Tile: M=128 rows, N=256 (fi cols 0-127,
// fj cols 128-255), K=128 staged in smem as tf32 bits, row pad 132 (conflict-
// free fragment LDS). Warp grid 4(M)x4(N), warp tile 32x64, m16n8k8 mma.
// Epilogue: accum -> smem (reuse), then bias/relu/att dots/sigmoid, writes
// out = fi + sigmoid(a1+a2)*fj, plus fj/a1/a2 scratch.
// ---------------------------------------------------------------------------
#define XPAD 132
#define OPAD 264

__global__ __launch_bounds__(512, 1)
void gat_gemm_kernel(const float* __restrict__ X,
                     const float* __restrict__ W1, const float* __restrict__ b1,
                     const float* __restrict__ W2, const float* __restrict__ b2,
                     const float* __restrict__ wa1, const float* __restrict__ ba1,
                     const float* __restrict__ wa2, const float* __restrict__ ba2,
                     float* __restrict__ out, int N)
{
    extern __shared__ uint32_t smem_u[];
    uint32_t* xs = smem_u;                    // [128][XPAD] tf32 bits of X tile
    uint32_t* ws = smem_u + 128 * XPAD;       // [256][XPAD]: W1 rows 0-127, W2 rows 128-255
    float*    osm = (float*)smem_u;           // stage-2 view: [128][OPAD]

    const int tid  = threadIdx.x;
    const int warp = tid >> 5;
    const int lane = tid & 31;
    const int g    = lane >> 2;    // group 0..7
    const int tig  = lane & 3;     // thread-in-group 0..3
    const int wm   = warp & 3;     // M warp tile (32 rows each)
    const int wn   = warp >> 2;    // N warp tile (64 cols each of 256)
    const int row0 = blockIdx.x * 128;

    // --- Stage X tile (rows row0..row0+127), tf32-convert, pad 132 ---
    const float4* Xv = (const float4*)X;
    for (int it = 0; it < 8; ++it) {
        int idx = tid + it * 512;           // 0..4095
        int r  = idx >> 5;
        int k4 = idx & 31;
        int row = row0 + r;
        float4 v = (row < N) ? Xv[(size_t)row * 32 + k4] : make_float4(0.f, 0.f, 0.f, 0.f);
        uint32_t* p = &xs[r * XPAD + k4 * 4];
        p[0] = f2tf32(v.x); p[1] = f2tf32(v.y); p[2] = f2tf32(v.z); p[3] = f2tf32(v.w);
    }
    // --- Stage W1, W2 (row-major [outcol][k]) ---
    const float4* W1v = (const float4*)W1;
    const float4* W2v = (const float4*)W2;
    for (int it = 0; it < 8; ++it) {
        int idx = tid + it * 512;
        int c  = idx >> 5;
        int k4 = idx & 31;
        float4 a = W1v[c * 32 + k4];
        uint32_t* p = &ws[c * XPAD + k4 * 4];
        p[0] = f2tf32(a.x); p[1] = f2tf32(a.y); p[2] = f2tf32(a.z); p[3] = f2tf32(a.w);
        float4 b = W2v[c * 32 + k4];
        uint32_t* q = &ws[(128 + c) * XPAD + k4 * 4];
        q[0] = f2tf32(b.x); q[1] = f2tf32(b.y); q[2] = f2tf32(b.z); q[3] = f2tf32(b.w);
    }
    __syncthreads();

    // --- Main mma loop ---
    float d[2][8][4];
#pragma unroll
    for (int t = 0; t < 2; ++t)
#pragma unroll
        for (int u = 0; u < 8; ++u)
#pragma unroll
            for (int e = 0; e < 4; ++e) d[t][u][e] = 0.f;

    const int m0 = wm * 32;
    const uint32_t* wsn = ws + (size_t)(wn * 64) * XPAD;   // this warp's 64 output cols

#pragma unroll
    for (int kk = 0; kk < 16; ++kk) {
        const int k0 = kk * 8;
        uint32_t a[2][4];
#pragma unroll
        for (int t = 0; t < 2; ++t) {
            int r = m0 + t * 16 + g;
            a[t][0] = xs[r * XPAD + k0 + tig];
            a[t][1] = xs[(r + 8) * XPAD + k0 + tig];
            a[t][2] = xs[r * XPAD + k0 + tig + 4];
            a[t][3] = xs[(r + 8) * XPAD + k0 + tig + 4];
        }
        uint32_t b[8][2];
#pragma unroll
        for (int u = 0; u < 8; ++u) {
            int n = u * 8 + g;
            b[u][0] = wsn[n * XPAD + k0 + tig];
            b[u][1] = wsn[n * XPAD + k0 + tig + 4];
        }
#pragma unroll
        for (int t = 0; t < 2; ++t)
#pragma unroll
            for (int u = 0; u < 8; ++u)
                mma_tf32(d[t][u][0], d[t][u][1], d[t][u][2], d[t][u][3],
                         a[t][0], a[t][1], a[t][2], a[t][3], b[u][0], b[u][1]);
    }

    __syncthreads();   // done reading xs/ws; reuse smem as output stage

    // --- Stage accums to smem: osm[r][c], c 0-127 = fi, 128-255 = fj ---
    const int nout0 = wn * 64;
#pragma unroll
    for (int t = 0; t < 2; ++t) {
        int r = m0 + t * 16 + g;
#pragma unroll
        for (int u = 0; u < 8; ++u) {
            int c = nout0 + u * 8 + tig * 2;
            osm[r * OPAD + c]           = d[t][u][0];
            osm[r * OPAD + c + 1]       = d[t][u][1];
            osm[(r + 8) * OPAD + c]     = d[t][u][2];
            osm[(r + 8) * OPAD + c + 1] = d[t][u][3];
        }
    }
    __syncthreads();

    // --- Stage 2: per-row epilogue. thread -> (row = tid/4, quarter q = tid%4) ---
    const int row = tid >> 2;
    const int q   = tid & 3;
    const int gr  = row0 + row;
    const float4* fi4 = (const float4*)(osm + row * OPAD + q * 32);
    const float4* fj4 = (const float4*)(osm + row * OPAD + 128 + q * 32);
    const float4* b1v  = (const float4*)(b1  + q * 32);
    const float4* b2v  = (const float4*)(b2  + q * 32);
    const float4* wa1v = (const float4*)(wa1 + q * 32);
    const float4* wa2v = (const float4*)(wa2 + q * 32);

    // pass A: attention dots
    float p1 = 0.f, p2 = 0.f;
#pragma unroll
    for (int i = 0; i < 8; ++i) {
        float4 f = fi4[i], j = fj4[i];
        float4 bb1 = b1v[i], bb2 = b2v[i], v1 = wa1v[i], v2 = wa2v[i];
        float fx = fmaxf(f.x + bb1.x, 0.f), fy = fmaxf(f.y + bb1.y, 0.f);
        float fz = fmaxf(f.z + bb1.z, 0.f), fw = fmaxf(f.w + bb1.w, 0.f);
        float jx = fmaxf(j.x + bb2.x, 0.f), jy = fmaxf(j.y + bb2.y, 0.f);
        float jz = fmaxf(j.z + bb2.z, 0.f), jw = fmaxf(j.w + bb2.w, 0.f);
        p1 = fmaf(fx, v1.x, fmaf(fy, v1.y, fmaf(fz, v1.z, fmaf(fw, v1.w, p1))));
        p2 = fmaf(jx, v2.x, fmaf(jy, v2.y, fmaf(jz, v2.z, fmaf(jw, v2.w, p2))));
    }
    p1 += __shfl_xor_sync(0xffffffffu, p1, 1, 4);
    p1 += __shfl_xor_sync(0xffffffffu, p1, 2, 4);
    p2 += __shfl_xor_sync(0xffffffffu, p2, 1, 4);
    p2 += __shfl_xor_sync(0xffffffffu, p2, 2, 4);

    float a1v = p1 + ba1[0];
    float a2v = p2 + ba2[0];
    float att = sigmoidf_(a1v + a2v);
    if (gr < N && q == 0) { g_a1[gr] = a1v; g_a2[gr] = a2v; }

    // pass B: out = relu(fi) + att*relu(fj); g_fj = relu(fj)
    if (gr < N) {
        float4* op = (float4*)(out + (size_t)gr * D + q * 32);
        float4* jp = (float4*)(g_fj + (size_t)gr * D + q * 32);
#pragma unroll
        for (int i = 0; i < 8; ++i) {
            float4 f = fi4[i], j = fj4[i];
            float4 bb1 = b1v[i], bb2 = b2v[i];
            float4 jr, o;
            jr.x = fmaxf(j.x + bb2.x, 0.f);
            jr.y = fmaxf(j.y + bb2.y, 0.f);
            jr.z = fmaxf(j.z + bb2.z, 0.f);
            jr.w = fmaxf(j.w + bb2.w, 0.f);
            o.x = fmaf(att, jr.x, fmaxf(f.x + bb1.x, 0.f));
            o.y = fmaf(att, jr.y, fmaxf(f.y + bb1.y, 0.f));
            o.z = fmaf(att, jr.z, fmaxf(f.z + bb1.z, 0.f));
            o.w = fmaf(att, jr.w, fmaxf(f.w + bb1.w, 0.f));
            op[i] = o;
            jp[i] = jr;
        }
    }
}

// ---------------------------------------------------------------------------
// CSR build
// ---------------------------------------------------------------------------
__global__ void zero_cnt_kernel(int N) {
    int t = blockIdx.x * blockDim.x + threadIdx.x;
    if (t < N) g_cnt[t] = 0;
}

__global__ void hist_kernel(const int* __restrict__ ei, int E, int N) {
    int e = blockIdx.x * blockDim.x + threadIdx.x;
    if (e >= E) return;
    int i = ei[e];
    if ((unsigned)i < (unsigned)N) atomicAdd(&g_cnt[i], 1);
}

// Single-block exclusive scan, fully smem-staged (coalesced global access).
__global__ __launch_bounds__(1024)
void scan_kernel(int N) {
    extern __shared__ int s[];
    int* partial = s + MAXN;
    const int t = threadIdx.x;

    for (int i = t; i < N; i += 1024) s[i] = g_cnt[i];
    __syncthreads();

    const int chunk = (N + 1023) / 1024;
    const int start = t * chunk;
    const int end   = min(start + chunk, N);
    int sum = 0;
    for (int i = start; i < end; ++i) { int c = s[i]; s[i] = sum; sum += c; }
    partial[t] = sum;
    __syncthreads();

    for (int off = 1; off < 1024; off <<= 1) {
        int v = (t >= off) ? partial[t - off] : 0;
        __syncthreads();
        partial[t] += v;
        __syncthreads();
    }

    int offs = partial[t] - sum;
    for (int i = start; i < end; ++i) s[i] += offs;
    __syncthreads();

    for (int i = t; i < N; i += 1024) {
        int r = s[i];
        g_rowptr[i] = r;
        g_cursor[i] = r;
    }
    if (t == 1023) g_rowptr[N] = partial[1023];
}

__global__ void fill_kernel(const int* __restrict__ ei, int E, int N) {
    int e = blockIdx.x * blockDim.x + threadIdx.x;
    if (e >= E) return;
    int i = ei[e];
    int j = ei[E + e];
    if ((unsigned)i >= (unsigned)N || (unsigned)j >= (unsigned)N) return;
    int pos = atomicAdd(&g_cursor[i], 1);
    g_col[pos]  = j;
    g_attw[pos] = sigmoidf_(g_a1[i] + g_a2[j]);
}

// ---------------------------------------------------------------------------
// Gather: one warp per destination node. No output atomics.
// ---------------------------------------------------------------------------
__global__ __launch_bounds__(256)
void gat_gather_kernel(float* __restrict__ out, int N) {
    int w = (int)((blockIdx.x * blockDim.x + threadIdx.x) >> 5);
    if (w >= N) return;
    int lane = threadIdx.x & 31;

    int beg = g_rowptr[w];
    int endp = g_rowptr[w + 1];
    if (beg == endp) return;

    const float4* fj4 = (const float4*)g_fj;
    float4 acc = make_float4(0.f, 0.f, 0.f, 0.f);

    for (int base = beg; base < endp; base += 32) {
        int idx = base + lane;
        int j = 0;
        float att = 0.f;
        if (idx < endp) { j = g_col[idx]; att = g_attw[idx]; }
        int cnt = min(32, endp - base);
        for (int k = 0; k < cnt; ++k) {
            int   jj = __shfl_sync(0xffffffffu, j, k);
            float aa = __shfl_sync(0xffffffffu, att, k);
            float4 v = fj4[(size_t)jj * 32 + lane];
            acc.x = fmaf(aa, v.x, acc.x);
            acc.y = fmaf(aa, v.y, acc.y);
            acc.z = fmaf(aa, v.z, acc.z);
            acc.w = fmaf(aa, v.w, acc.w);
        }
    }

    float4* o = (float4*)&out[(size_t)w * D + lane * 4];
    float4 cur = *o;
    cur.x += acc.x; cur.y += acc.y; cur.z += acc.z; cur.w += acc.w;
    *o = cur;
}

// ---------------------------------------------------------------------------
extern "C" void kernel_launch(void* const* d_in, const int* in_sizes, int n_in,
                              void* d_out, int out_size)
{
    const float* X   = (const float*)d_in[0];
    const float* W1  = (const float*)d_in[1];
    const float* b1  = (const float*)d_in[2];
    const float* W2  = (const float*)d_in[3];
    const float* b2  = (const float*)d_in[4];
    const float* wa1 = (const float*)d_in[5];
    const float* ba1 = (const float*)d_in[6];
    const float* wa2 = (const float*)d_in[7];
    const float* ba2 = (const float*)d_in[8];
    const int*   ei  = (const int*)d_in[9];   // int32 edge_index [2, E]
    float* out = (float*)d_out;

    int N = in_sizes[0] / D;
    int E = in_sizes[9] / 2;

    const int gemm_smem = (128 * XPAD + 256 * XPAD) * (int)sizeof(uint32_t); // ~198 KB
    cudaFuncSetAttribute(gat_gemm_kernel,
                         cudaFuncAttributeMaxDynamicSharedMemorySize, gemm_smem);
    const int scan_smem = (MAXN + 1024) * (int)sizeof(int);                  // ~204 KB
    cudaFuncSetAttribute(scan_kernel,
                         cudaFuncAttributeMaxDynamicSharedMemorySize, scan_smem);

    // 1) GEMM (produces fi->out with self-loop, fj/a1/a2 scratch)
    gat_gemm_kernel<<<(N + 127) / 128, 512, gemm_smem>>>(
        X, W1, b1, W2, b2, wa1, ba1, wa2, ba2, out, N);

    // 2) CSR build
    zero_cnt_kernel<<<(N + 255) / 256, 256>>>(N);
    hist_kernel<<<(E + 255) / 256, 256>>>(ei, E, N);
    scan_kernel<<<1, 1024, scan_smem>>>(N);
    fill_kernel<<<(E + 255) / 256, 256>>>(ei, E, N);

    // 3) Gather (one warp per node, no atomics)
    gat_gather_kernel<<<(N * 32 + 255) / 256, 256>>>(out, N);
}

// round 7
// speedup vs baseline: 2.4671x; 1.0194x over previous
#include <cuda_runtime.h>
#include <cuda_bf16.h>
#include <cstdint>

#define D 128
#define MAXN 50000
#define MAXE 800000

// Scratch (allocation-free rule: __device__ globals)
__device__ float g_fj[MAXN * D];
__device__ float g_a1[MAXN];
__device__ float g_a2[MAXN];
__device__ int   g_cnt[MAXN];
__device__ int   g_rowptr[MAXN + 1];
__device__ int   g_cursor[MAXN];
__device__ int   g_col[MAXE];
__device__ float g_attw[MAXE];
__device__ uint32_t g_xt[MAXN * D];        // tf32 bits of X
__device__ uint32_t g_wt[2 * D * D];       // tf32 bits of W1 (rows 0-127), W2 (128-255)
__device__ int   g_bsum[256];
__device__ int   g_boff[256];

__device__ __forceinline__ float sigmoidf_(float x) {
    return 1.0f / (1.0f + __expf(-x));
}

__device__ __forceinline__ uint32_t f2tf32(float x) {
    uint32_t r;
    asm("cvt.rna.tf32.f32 %0, %1;" : "=r"(r) : "f"(x));
    return r;
}

__device__ __forceinline__ void mma_tf32(float& d0, float& d1, float& d2, float& d3,
                                         uint32_t a0, uint32_t a1, uint32_t a2, uint32_t a3,
                                         uint32_t b0, uint32_t b1) {
    asm volatile("mma.sync.aligned.m16n8k8.row.col.f32.tf32.tf32.f32 "
                 "{%0,%1,%2,%3},{%4,%5,%6,%7},{%8,%9},{%0,%1,%2,%3};"
                 : "+f"(d0), "+f"(d1), "+f"(d2), "+f"(d3)
                 : "r"(a0), "r"(a1), "r"(a2), "r"(a3), "r"(b0), "r"(b1));
}

// ---------------------------------------------------------------------------
// Setup: tf32-convert X and W once; zero histogram counts.
// ---------------------------------------------------------------------------
__global__ __launch_bounds__(256)
void convert_kernel(const float* __restrict__ X,
                    const float* __restrict__ W1, const float* __restrict__ W2,
                    int N)
{
    const int stride = gridDim.x * blockDim.x;
    const int t0 = blockIdx.x * blockDim.x + threadIdx.x;

    // X -> tf32 bits
    const float4* Xv = (const float4*)X;
    uint4* xo = (uint4*)g_xt;
    const int nx4 = N * 32;
    for (int i = t0; i < nx4; i += stride) {
        float4 v = Xv[i];
        xo[i] = make_uint4(f2tf32(v.x), f2tf32(v.y), f2tf32(v.z), f2tf32(v.w));
    }
    // W1,W2 -> tf32 bits
    const float4* W1v = (const float4*)W1;
    const float4* W2v = (const float4*)W2;
    uint4* wo = (uint4*)g_wt;
    for (int i = t0; i < D * 32; i += stride) {
        float4 a = W1v[i];
        wo[i] = make_uint4(f2tf32(a.x), f2tf32(a.y), f2tf32(a.z), f2tf32(a.w));
        float4 b = W2v[i];
        wo[D * 32 + i] = make_uint4(f2tf32(b.x), f2tf32(b.y), f2tf32(b.z), f2tf32(b.w));
    }
    // zero counts
    for (int i = t0; i < N; i += stride) g_cnt[i] = 0;
}

// ---------------------------------------------------------------------------
// tf32 tensor-core GEMM + epilogue (stages pre-converted bits; no cvt).
// ---------------------------------------------------------------------------
#define XPAD 132
#define OPAD 264

__global__ __launch_bounds__(512, 1)
void gat_gemm_kernel(const float* __restrict__ b1, const float* __restrict__ b2,
                     const float* __restrict__ wa1, const float* __restrict__ ba1,
                     const float* __restrict__ wa2, const float* __restrict__ ba2,
                     float* __restrict__ out, int N)
{
    extern __shared__ uint32_t smem_u[];
    uint32_t* xs = smem_u;                    // [128][XPAD]
    uint32_t* ws = smem_u + 128 * XPAD;       // [256][XPAD]
    float*    osm = (float*)smem_u;           // stage-2 view: [128][OPAD]

    const int tid  = threadIdx.x;
    const int warp = tid >> 5;
    const int lane = tid & 31;
    const int g    = lane >> 2;
    const int tig  = lane & 3;
    const int wm   = warp & 3;
    const int wn   = warp >> 2;
    const int row0 = blockIdx.x * 128;

    // --- Stage X tile (pre-converted bits) ---
    const uint4* Xv = (const uint4*)g_xt;
    for (int it = 0; it < 8; ++it) {
        int idx = tid + it * 512;
        int r  = idx >> 5;
        int k4 = idx & 31;
        int row = row0 + r;
        uint4 v = (row < N) ? Xv[(size_t)row * 32 + k4] : make_uint4(0u, 0u, 0u, 0u);
        *(uint4*)&xs[r * XPAD + k4 * 4] = v;
    }
    // --- Stage W (pre-converted bits) ---
    const uint4* Wv = (const uint4*)g_wt;
    for (int it = 0; it < 16; ++it) {
        int idx = tid + it * 512;          // 0..8191 -> c 0..255, k4 0..31
        int c  = idx >> 5;
        int k4 = idx & 31;
        *(uint4*)&ws[c * XPAD + k4 * 4] = Wv[idx];
    }
    __syncthreads();

    // --- Main mma loop ---
    float d[2][8][4];
#pragma unroll
    for (int t = 0; t < 2; ++t)
#pragma unroll
        for (int u = 0; u < 8; ++u)
#pragma unroll
            for (int e = 0; e < 4; ++e) d[t][u][e] = 0.f;

    const int m0 = wm * 32;
    const uint32_t* wsn = ws + (size_t)(wn * 64) * XPAD;

#pragma unroll
    for (int kk = 0; kk < 16; ++kk) {
        const int k0 = kk * 8;
        uint32_t a[2][4];
#pragma unroll
        for (int t = 0; t < 2; ++t) {
            int r = m0 + t * 16 + g;
            a[t][0] = xs[r * XPAD + k0 + tig];
            a[t][1] = xs[(r + 8) * XPAD + k0 + tig];
            a[t][2] = xs[r * XPAD + k0 + tig + 4];
            a[t][3] = xs[(r + 8) * XPAD + k0 + tig + 4];
        }
        uint32_t b[8][2];
#pragma unroll
        for (int u = 0; u < 8; ++u) {
            int n = u * 8 + g;
            b[u][0] = wsn[n * XPAD + k0 + tig];
            b[u][1] = wsn[n * XPAD + k0 + tig + 4];
        }
#pragma unroll
        for (int t = 0; t < 2; ++t)
#pragma unroll
            for (int u = 0; u < 8; ++u)
                mma_tf32(d[t][u][0], d[t][u][1], d[t][u][2], d[t][u][3],
                         a[t][0], a[t][1], a[t][2], a[t][3], b[u][0], b[u][1]);
    }

    __syncthreads();

    // --- Stage accums to smem ---
    const int nout0 = wn * 64;
#pragma unroll
    for (int t = 0; t < 2; ++t) {
        int r = m0 + t * 16 + g;
#pragma unroll
        for (int u = 0; u < 8; ++u) {
            int c = nout0 + u * 8 + tig * 2;
            osm[r * OPAD + c]           = d[t][u][0];
            osm[r * OPAD + c + 1]       = d[t][u][1];
            osm[(r + 8) * OPAD + c]     = d[t][u][2];
            osm[(r + 8) * OPAD + c + 1] = d[t][u][3];
        }
    }
    __syncthreads();

    // --- Stage 2: per-row epilogue ---
    const int row = tid >> 2;
    const int q   = tid & 3;
    const int gr  = row0 + row;
    const float4* fi4 = (const float4*)(osm + row * OPAD + q * 32);
    const float4* fj4 = (const float4*)(osm + row * OPAD + 128 + q * 32);
    const float4* b1v  = (const float4*)(b1  + q * 32);
    const float4* b2v  = (const float4*)(b2  + q * 32);
    const float4* wa1v = (const float4*)(wa1 + q * 32);
    const float4* wa2v = (const float4*)(wa2 + q * 32);

    float p1 = 0.f, p2 = 0.f;
#pragma unroll
    for (int i = 0; i < 8; ++i) {
        float4 f = fi4[i], j = fj4[i];
        float4 bb1 = b1v[i], bb2 = b2v[i], v1 = wa1v[i], v2 = wa2v[i];
        float fx = fmaxf(f.x + bb1.x, 0.f), fy = fmaxf(f.y + bb1.y, 0.f);
        float fz = fmaxf(f.z + bb1.z, 0.f), fw = fmaxf(f.w + bb1.w, 0.f);
        float jx = fmaxf(j.x + bb2.x, 0.f), jy = fmaxf(j.y + bb2.y, 0.f);
        float jz = fmaxf(j.z + bb2.z, 0.f), jw = fmaxf(j.w + bb2.w, 0.f);
        p1 = fmaf(fx, v1.x, fmaf(fy, v1.y, fmaf(fz, v1.z, fmaf(fw, v1.w, p1))));
        p2 = fmaf(jx, v2.x, fmaf(jy, v2.y, fmaf(jz, v2.z, fmaf(jw, v2.w, p2))));
    }
    p1 += __shfl_xor_sync(0xffffffffu, p1, 1, 4);
    p1 += __shfl_xor_sync(0xffffffffu, p1, 2, 4);
    p2 += __shfl_xor_sync(0xffffffffu, p2, 1, 4);
    p2 += __shfl_xor_sync(0xffffffffu, p2, 2, 4);

    float a1v = p1 + ba1[0];
    float a2v = p2 + ba2[0];
    float att = sigmoidf_(a1v + a2v);
    if (gr < N && q == 0) { g_a1[gr] = a1v; g_a2[gr] = a2v; }

    if (gr < N) {
        float4* op = (float4*)(out + (size_t)gr * D + q * 32);
        float4* jp = (float4*)(g_fj + (size_t)gr * D + q * 32);
#pragma unroll
        for (int i = 0; i < 8; ++i) {
            float4 f = fi4[i], j = fj4[i];
            float4 bb1 = b1v[i], bb2 = b2v[i];
            float4 jr, o;
            jr.x = fmaxf(j.x + bb2.x, 0.f);
            jr.y = fmaxf(j.y + bb2.y, 0.f);
            jr.z = fmaxf(j.z + bb2.z, 0.f);
            jr.w = fmaxf(j.w + bb2.w, 0.f);
            o.x = fmaf(att, jr.x, fmaxf(f.x + bb1.x, 0.f));
            o.y = fmaf(att, jr.y, fmaxf(f.y + bb1.y, 0.f));
            o.z = fmaf(att, jr.z, fmaxf(f.z + bb1.z, 0.f));
            o.w = fmaf(att, jr.w, fmaxf(f.w + bb1.w, 0.f));
            op[i] = o;
            jp[i] = jr;
        }
    }
}

// ---------------------------------------------------------------------------
// CSR build
// ---------------------------------------------------------------------------
__global__ void hist_kernel(const int* __restrict__ ei, int E, int N) {
    int e = blockIdx.x * blockDim.x + threadIdx.x;
    if (e >= E) return;
    int i = ei[e];
    if ((unsigned)i < (unsigned)N) atomicAdd(&g_cnt[i], 1);
}

// Parallel 3-phase scan: per-block sums -> scan partials -> per-block scan.
__global__ __launch_bounds__(256)
void scan1_kernel(int N) {
    __shared__ int red[256];
    int i = blockIdx.x * 256 + threadIdx.x;
    int v = (i < N) ? g_cnt[i] : 0;
    red[threadIdx.x] = v;
    __syncthreads();
    for (int off = 128; off >= 1; off >>= 1) {
        if (threadIdx.x < off) red[threadIdx.x] += red[threadIdx.x + off];
        __syncthreads();
    }
    if (threadIdx.x == 0) g_bsum[blockIdx.x] = red[0];
}

__global__ __launch_bounds__(256)
void scan2_kernel(int nb, int N) {
    __shared__ int p[256];
    int t = threadIdx.x;
    int v = (t < nb) ? g_bsum[t] : 0;
    p[t] = v;
    __syncthreads();
    for (int off = 1; off < 256; off <<= 1) {
        int u = (t >= off) ? p[t - off] : 0;
        __syncthreads();
        p[t] += u;
        __syncthreads();
    }
    if (t < nb) g_boff[t] = p[t] - v;           // exclusive block offset
    if (t == nb - 1) g_rowptr[N] = p[t];        // total
}

__global__ __launch_bounds__(256)
void scan3_kernel(int N) {
    __shared__ int p[256];
    int t = threadIdx.x;
    int i = blockIdx.x * 256 + t;
    int v = (i < N) ? g_cnt[i] : 0;
    p[t] = v;
    __syncthreads();
    for (int off = 1; off < 256; off <<= 1) {
        int u = (t >= off) ? p[t - off] : 0;
        __syncthreads();
        p[t] += u;
        __syncthreads();
    }
    if (i < N) {
        int excl = p[t] - v + g_boff[blockIdx.x];
        g_rowptr[i] = excl;
        g_cursor[i] = excl;
    }
}

__global__ void fill_kernel(const int* __restrict__ ei, int E, int N) {
    int e = blockIdx.x * blockDim.x + threadIdx.x;
    if (e >= E) return;
    int i = ei[e];
    int j = ei[E + e];
    if ((unsigned)i >= (unsigned)N || (unsigned)j >= (unsigned)N) return;
    int pos = atomicAdd(&g_cursor[i], 1);
    g_col[pos]  = j;
    g_attw[pos] = sigmoidf_(g_a1[i] + g_a2[j]);
}

// ---------------------------------------------------------------------------
// Gather: one warp per destination node. No output atomics.
// ---------------------------------------------------------------------------
__global__ __launch_bounds__(256)
void gat_gather_kernel(float* __restrict__ out, int N) {
    int w = (int)((blockIdx.x * blockDim.x + threadIdx.x) >> 5);
    if (w >= N) return;
    int lane = threadIdx.x & 31;

    int beg = g_rowptr[w];
    int endp = g_rowptr[w + 1];
    if (beg == endp) return;

    const float4* fj4 = (const float4*)g_fj;
    float4 acc = make_float4(0.f, 0.f, 0.f, 0.f);

    for (int base = beg; base < endp; base += 32) {
        int idx = base + lane;
        int j = 0;
        float att = 0.f;
        if (idx < endp) { j = g_col[idx]; att = g_attw[idx]; }
        int cnt = min(32, endp - base);
        for (int k = 0; k < cnt; ++k) {
            int   jj = __shfl_sync(0xffffffffu, j, k);
            float aa = __shfl_sync(0xffffffffu, att, k);
            float4 v = fj4[(size_t)jj * 32 + lane];
            acc.x = fmaf(aa, v.x, acc.x);
            acc.y = fmaf(aa, v.y, acc.y);
            acc.z = fmaf(aa, v.z, acc.z);
            acc.w = fmaf(aa, v.w, acc.w);
        }
    }

    float4* o = (float4*)&out[(size_t)w * D + lane * 4];
    float4 cur = *o;
    cur.x += acc.x; cur.y += acc.y; cur.z += acc.z; cur.w += acc.w;
    *o = cur;
}

// ---------------------------------------------------------------------------
extern "C" void kernel_launch(void* const* d_in, const int* in_sizes, int n_in,
                              void* d_out, int out_size)
{
    const float* X   = (const float*)d_in[0];
    const float* W1  = (const float*)d_in[1];
    const float* b1  = (const float*)d_in[2];
    const float* W2  = (const float*)d_in[3];
    const float* b2  = (const float*)d_in[4];
    const float* wa1 = (const float*)d_in[5];
    const float* ba1 = (const float*)d_in[6];
    const float* wa2 = (const float*)d_in[7];
    const float* ba2 = (const float*)d_in[8];
    const int*   ei  = (const int*)d_in[9];   // int32 edge_index [2, E]
    float* out = (float*)d_out;

    int N = in_sizes[0] / D;
    int E = in_sizes[9] / 2;

    const int gemm_smem = (128 * XPAD + 256 * XPAD) * (int)sizeof(uint32_t); // ~198 KB
    cudaFuncSetAttribute(gat_gemm_kernel,
                         cudaFuncAttributeMaxDynamicSharedMemorySize, gemm_smem);

    // 0) tf32 convert (X, W) + zero counts
    convert_kernel<<<1024, 256>>>(X, W1, W2, N);

    // 1) GEMM (produces fi->out with self-loop, fj/a1/a2 scratch)
    gat_gemm_kernel<<<(N + 127) / 128, 512, gemm_smem>>>(
        b1, b2, wa1, ba1, wa2, ba2, out, N);

    // 2) CSR build
    int nb = (N + 255) / 256;                    // <= 256
    hist_kernel<<<(E + 255) / 256, 256>>>(ei, E, N);
    scan1_kernel<<<nb, 256>>>(N);
    scan2_kernel<<<1, 256>>>(nb, N);
    scan3_kernel<<<nb, 256>>>(N);
    fill_kernel<<<(E + 255) / 256, 256>>>(ei, E, N);

    // 3) Gather (one warp per node, no atomics)
    gat_gather_kernel<<<(N * 32 + 255) / 256, 256>>>(out, N);
}

// round 8
// speedup vs baseline: 3.3502x; 1.3580x over previous
#include <cuda_runtime.h>
#include <cuda_bf16.h>
#include <cstdint>

#define D 128
#define MAXN 50000
#define MAXE 800000
#define XPAD 132

// Scratch (allocation-free rule: __device__ globals)
__device__ float g_fj[MAXN * D];
__device__ float g_a1[MAXN];
__device__ float g_a2[MAXN];
__device__ int   g_cnt[MAXN];
__device__ int   g_rowptr[MAXN + 1];
__device__ int   g_cursor[MAXN];
__device__ int   g_col[MAXE];
__device__ float g_attw[MAXE];
__device__ uint32_t g_xt[MAXN * D];        // tf32 bits of X
__device__ uint32_t g_wt[2 * D * D];       // tf32 bits of W1 (rows 0-127), W2 (128-255)
__device__ int   g_bsum[256];

__device__ __forceinline__ float sigmoidf_(float x) {
    return 1.0f / (1.0f + __expf(-x));
}

__device__ __forceinline__ uint32_t f2tf32(float x) {
    uint32_t r;
    asm("cvt.rna.tf32.f32 %0, %1;" : "=r"(r) : "f"(x));
    return r;
}

__device__ __forceinline__ void mma_tf32(float& d0, float& d1, float& d2, float& d3,
                                         uint32_t a0, uint32_t a1, uint32_t a2, uint32_t a3,
                                         uint32_t b0, uint32_t b1) {
    asm volatile("mma.sync.aligned.m16n8k8.row.col.f32.tf32.tf32.f32 "
                 "{%0,%1,%2,%3},{%4,%5,%6,%7},{%8,%9},{%0,%1,%2,%3};"
                 : "+f"(d0), "+f"(d1), "+f"(d2), "+f"(d3)
                 : "r"(a0), "r"(a1), "r"(a2), "r"(a3), "r"(b0), "r"(b1));
}

// ---------------------------------------------------------------------------
// Setup: tf32-convert X and W once; zero histogram counts.
// ---------------------------------------------------------------------------
__global__ __launch_bounds__(256)
void convert_kernel(const float* __restrict__ X,
                    const float* __restrict__ W1, const float* __restrict__ W2,
                    int N)
{
    const int stride = gridDim.x * blockDim.x;
    const int t0 = blockIdx.x * blockDim.x + threadIdx.x;

    const float4* Xv = (const float4*)X;
    uint4* xo = (uint4*)g_xt;
    const int nx4 = N * 32;
    for (int i = t0; i < nx4; i += stride) {
        float4 v = Xv[i];
        xo[i] = make_uint4(f2tf32(v.x), f2tf32(v.y), f2tf32(v.z), f2tf32(v.w));
    }
    const float4* W1v = (const float4*)W1;
    const float4* W2v = (const float4*)W2;
    uint4* wo = (uint4*)g_wt;
    for (int i = t0; i < D * 32; i += stride) {
        float4 a = W1v[i];
        wo[i] = make_uint4(f2tf32(a.x), f2tf32(a.y), f2tf32(a.z), f2tf32(a.w));
        float4 b = W2v[i];
        wo[D * 32 + i] = make_uint4(f2tf32(b.x), f2tf32(b.y), f2tf32(b.z), f2tf32(b.w));
    }
    for (int i = t0; i < N; i += stride) g_cnt[i] = 0;
}

// ---------------------------------------------------------------------------
// Persistent tf32 GEMM. 512 thr (16 warps = 4 wm x 4 wn). Tile M=128.
// Warp (wm,wn): rows wm*32..+31, cols wn*32..+31 of BOTH fi (u 0-3) and fj
// (u 4-7) -> epilogue entirely in registers except 8KB dot-partial smem.
// W staged once per block; X per tile.
// ---------------------------------------------------------------------------
__global__ __launch_bounds__(512, 1)
void gat_gemm_kernel(const float* __restrict__ b1, const float* __restrict__ b2,
                     const float* __restrict__ wa1, const float* __restrict__ ba1,
                     const float* __restrict__ wa2, const float* __restrict__ ba2,
                     float* __restrict__ out, int N, int tiles)
{
    extern __shared__ uint32_t smem_u[];
    uint32_t* ws  = smem_u;                        // [256][XPAD]
    uint32_t* xs  = smem_u + 256 * XPAD;           // [128][XPAD]
    float*    sp1 = (float*)(xs + 128 * XPAD);     // [128][4]
    float*    sp2 = sp1 + 128 * 4;                 // [128][4]
    float*    satt = sp2 + 128 * 4;                // [128]

    const int tid  = threadIdx.x;
    const int warp = tid >> 5;
    const int lane = tid & 31;
    const int g    = lane >> 2;
    const int tig  = lane & 3;
    const int wm   = warp & 3;
    const int wn   = warp >> 2;
    const int m0   = wm * 32;

    // --- Stage W once ---
    const uint4* Wv = (const uint4*)g_wt;
    for (int it = 0; it < 16; ++it) {
        int idx = tid + it * 512;
        int c  = idx >> 5;
        int k4 = idx & 31;
        *(uint4*)&ws[c * XPAD + k4 * 4] = Wv[idx];
    }

    // Per-u W row offsets (cols wn*32.. of W1 for u<4, of W2 for u>=4)
    int woff[8];
#pragma unroll
    for (int u = 0; u < 8; ++u) {
        int nb = (u < 4) ? (wn * 32 + u * 8 + g) : (128 + wn * 32 + (u - 4) * 8 + g);
        woff[u] = nb * XPAD;
    }

    // Per-thread epilogue constants for cols c = wn*32 + u'*8 + tig*2 (+1)
    float2 bb1[4], bb2[4], v1[4], v2[4];
#pragma unroll
    for (int u = 0; u < 4; ++u) {
        int c = wn * 32 + u * 8 + tig * 2;
        bb1[u] = *(const float2*)&b1[c];
        bb2[u] = *(const float2*)&b2[c];
        v1[u]  = *(const float2*)&wa1[c];
        v2[u]  = *(const float2*)&wa2[c];
    }
    const float bba1 = ba1[0];
    const float bba2 = ba2[0];

    const uint4* Xv = (const uint4*)g_xt;

    for (int tile = blockIdx.x; tile < tiles; tile += gridDim.x) {
        const int row0 = tile * 128;

        // --- Stage X tile ---
        for (int it = 0; it < 8; ++it) {
            int idx = tid + it * 512;
            int r  = idx >> 5;
            int k4 = idx & 31;
            int row = row0 + r;
            uint4 v = (row < N) ? Xv[(size_t)row * 32 + k4] : make_uint4(0u, 0u, 0u, 0u);
            *(uint4*)&xs[r * XPAD + k4 * 4] = v;
        }
        __syncthreads();   // sync1: X staged (also: prev-tile smem consumers done)

        // --- mma ---
        float d[2][8][4];
#pragma unroll
        for (int t = 0; t < 2; ++t)
#pragma unroll
            for (int u = 0; u < 8; ++u)
#pragma unroll
                for (int e = 0; e < 4; ++e) d[t][u][e] = 0.f;

#pragma unroll
        for (int kk = 0; kk < 16; ++kk) {
            const int k0 = kk * 8;
            uint32_t a[2][4];
#pragma unroll
            for (int t = 0; t < 2; ++t) {
                int r = m0 + t * 16 + g;
                a[t][0] = xs[r * XPAD + k0 + tig];
                a[t][1] = xs[(r + 8) * XPAD + k0 + tig];
                a[t][2] = xs[r * XPAD + k0 + tig + 4];
                a[t][3] = xs[(r + 8) * XPAD + k0 + tig + 4];
            }
            uint32_t b[8][2];
#pragma unroll
            for (int u = 0; u < 8; ++u) {
                b[u][0] = ws[woff[u] + k0 + tig];
                b[u][1] = ws[woff[u] + k0 + tig + 4];
            }
#pragma unroll
            for (int t = 0; t < 2; ++t)
#pragma unroll
                for (int u = 0; u < 8; ++u)
                    mma_tf32(d[t][u][0], d[t][u][1], d[t][u][2], d[t][u][3],
                             a[t][0], a[t][1], a[t][2], a[t][3], b[u][0], b[u][1]);
        }

        // --- Dot partials (in regs), reduce over tig, stash per (row, wn) ---
        float p1[2][2] = {{0.f, 0.f}, {0.f, 0.f}};   // [t][half]
        float p2[2][2] = {{0.f, 0.f}, {0.f, 0.f}};
#pragma unroll
        for (int t = 0; t < 2; ++t)
#pragma unroll
            for (int u = 0; u < 4; ++u) {
                float fi0 = fmaxf(d[t][u][0] + bb1[u].x, 0.f);
                float fi1 = fmaxf(d[t][u][1] + bb1[u].y, 0.f);
                float fi2 = fmaxf(d[t][u][2] + bb1[u].x, 0.f);
                float fi3 = fmaxf(d[t][u][3] + bb1[u].y, 0.f);
                float fj0 = fmaxf(d[t][u + 4][0] + bb2[u].x, 0.f);
                float fj1 = fmaxf(d[t][u + 4][1] + bb2[u].y, 0.f);
                float fj2 = fmaxf(d[t][u + 4][2] + bb2[u].x, 0.f);
                float fj3 = fmaxf(d[t][u + 4][3] + bb2[u].y, 0.f);
                p1[t][0] = fmaf(fi0, v1[u].x, fmaf(fi1, v1[u].y, p1[t][0]));
                p1[t][1] = fmaf(fi2, v1[u].x, fmaf(fi3, v1[u].y, p1[t][1]));
                p2[t][0] = fmaf(fj0, v2[u].x, fmaf(fj1, v2[u].y, p2[t][0]));
                p2[t][1] = fmaf(fj2, v2[u].x, fmaf(fj3, v2[u].y, p2[t][1]));
            }
#pragma unroll
        for (int off = 1; off <= 2; off <<= 1)
#pragma unroll
            for (int t = 0; t < 2; ++t)
#pragma unroll
                for (int h = 0; h < 2; ++h) {
                    p1[t][h] += __shfl_xor_sync(0xffffffffu, p1[t][h], off);
                    p2[t][h] += __shfl_xor_sync(0xffffffffu, p2[t][h], off);
                }
        if (tig == 0) {
#pragma unroll
            for (int t = 0; t < 2; ++t)
#pragma unroll
                for (int h = 0; h < 2; ++h) {
                    int r = m0 + t * 16 + g + h * 8;
                    sp1[r * 4 + wn] = p1[t][h];
                    sp2[r * 4 + wn] = p2[t][h];
                }
        }
        __syncthreads();   // sync2: partials ready

        // --- att per row ---
        if (tid < 128) {
            int r = tid;
            float a1v = sp1[r * 4] + sp1[r * 4 + 1] + sp1[r * 4 + 2] + sp1[r * 4 + 3] + bba1;
            float a2v = sp2[r * 4] + sp2[r * 4 + 1] + sp2[r * 4 + 2] + sp2[r * 4 + 3] + bba2;
            satt[r] = sigmoidf_(a1v + a2v);
            int gr = row0 + r;
            if (gr < N) { g_a1[gr] = a1v; g_a2[gr] = a2v; }
        }
        __syncthreads();   // sync3: att ready

        // --- Stores: out = relu(fi) + att*relu(fj); g_fj = relu(fj) ---
#pragma unroll
        for (int t = 0; t < 2; ++t)
#pragma unroll
            for (int h = 0; h < 2; ++h) {
                int r = m0 + t * 16 + g + h * 8;
                int gr = row0 + r;
                if (gr >= N) continue;
                float att = satt[r];
                float* orow = out  + (size_t)gr * D;
                float* jrow = g_fj + (size_t)gr * D;
#pragma unroll
                for (int u = 0; u < 4; ++u) {
                    int c = wn * 32 + u * 8 + tig * 2;
                    int e0 = h * 2, e1 = h * 2 + 1;
                    float fj0 = fmaxf(d[t][u + 4][e0] + bb2[u].x, 0.f);
                    float fj1 = fmaxf(d[t][u + 4][e1] + bb2[u].y, 0.f);
                    float o0 = fmaf(att, fj0, fmaxf(d[t][u][e0] + bb1[u].x, 0.f));
                    float o1 = fmaf(att, fj1, fmaxf(d[t][u][e1] + bb1[u].y, 0.f));
                    *(float2*)&orow[c] = make_float2(o0, o1);
                    *(float2*)&jrow[c] = make_float2(fj0, fj1);
                }
            }
        // next iteration's sync1 protects xs/sp/satt reuse
    }
}

// ---------------------------------------------------------------------------
// CSR build
// ---------------------------------------------------------------------------
__global__ void hist_kernel(const int* __restrict__ ei, int E, int N) {
    int e = blockIdx.x * blockDim.x + threadIdx.x;
    if (e >= E) return;
    int i = ei[e];
    if ((unsigned)i < (unsigned)N) atomicAdd(&g_cnt[i], 1);
}

__global__ __launch_bounds__(256)
void scan1_kernel(int N) {
    __shared__ int red[256];
    int i = blockIdx.x * 256 + threadIdx.x;
    int v = (i < N) ? g_cnt[i] : 0;
    red[threadIdx.x] = v;
    __syncthreads();
    for (int off = 128; off >= 1; off >>= 1) {
        if (threadIdx.x < off) red[threadIdx.x] += red[threadIdx.x + off];
        __syncthreads();
    }
    if (threadIdx.x == 0) g_bsum[blockIdx.x] = red[0];
}

// Merged: every block scans the partials (redundant, cheap), then local scan.
__global__ __launch_bounds__(256)
void scanB_kernel(int nb, int N) {
    __shared__ int p[256];
    __shared__ int boff;
    const int t = threadIdx.x;

    int v = (t < nb) ? g_bsum[t] : 0;
    p[t] = v;
    __syncthreads();
    for (int off = 1; off < 256; off <<= 1) {
        int u = (t >= off) ? p[t - off] : 0;
        __syncthreads();
        p[t] += u;
        __syncthreads();
    }
    if (t == (int)blockIdx.x) boff = p[t] - v;
    if (blockIdx.x == 0 && t == nb - 1) g_rowptr[N] = p[t];
    __syncthreads();

    int i = blockIdx.x * 256 + t;
    int c = (i < N) ? g_cnt[i] : 0;
    p[t] = c;
    __syncthreads();
    for (int off = 1; off < 256; off <<= 1) {
        int u = (t >= off) ? p[t - off] : 0;
        __syncthreads();
        p[t] += u;
        __syncthreads();
    }
    if (i < N) {
        int excl = p[t] - c + boff;
        g_rowptr[i] = excl;
        g_cursor[i] = excl;
    }
}

__global__ void fill_kernel(const int* __restrict__ ei, int E, int N) {
    int e = blockIdx.x * blockDim.x + threadIdx.x;
    if (e >= E) return;
    int i = ei[e];
    int j = ei[E + e];
    if ((unsigned)i >= (unsigned)N || (unsigned)j >= (unsigned)N) return;
    int pos = atomicAdd(&g_cursor[i], 1);
    g_col[pos]  = j;
    g_attw[pos] = sigmoidf_(g_a1[i] + g_a2[j]);
}

// ---------------------------------------------------------------------------
// Gather: one warp per destination node. No output atomics.
// ---------------------------------------------------------------------------
__global__ __launch_bounds__(256)
void gat_gather_kernel(float* __restrict__ out, int N) {
    int w = (int)((blockIdx.x * blockDim.x + threadIdx.x) >> 5);
    if (w >= N) return;
    int lane = threadIdx.x & 31;

    int beg = g_rowptr[w];
    int endp = g_rowptr[w + 1];
    if (beg == endp) return;

    const float4* fj4 = (const float4*)g_fj;
    float4 acc = make_float4(0.f, 0.f, 0.f, 0.f);

    for (int base = beg; base < endp; base += 32) {
        int idx = base + lane;
        int j = 0;
        float att = 0.f;
        if (idx < endp) { j = g_col[idx]; att = g_attw[idx]; }
        int cnt = min(32, endp - base);
        for (int k = 0; k < cnt; ++k) {
            int   jj = __shfl_sync(0xffffffffu, j, k);
            float aa = __shfl_sync(0xffffffffu, att, k);
            float4 v = fj4[(size_t)jj * 32 + lane];
            acc.x = fmaf(aa, v.x, acc.x);
            acc.y = fmaf(aa, v.y, acc.y);
            acc.z = fmaf(aa, v.z, acc.z);
            acc.w = fmaf(aa, v.w, acc.w);
        }
    }

    float4* o = (float4*)&out[(size_t)w * D + lane * 4];
    float4 cur = *o;
    cur.x += acc.x; cur.y += acc.y; cur.z += acc.z; cur.w += acc.w;
    *o = cur;
}

// ---------------------------------------------------------------------------
extern "C" void kernel_launch(void* const* d_in, const int* in_sizes, int n_in,
                              void* d_out, int out_size)
{
    const float* X   = (const float*)d_in[0];
    const float* W1  = (const float*)d_in[1];
    const float* b1  = (const float*)d_in[2];
    const float* W2  = (const float*)d_in[3];
    const float* b2  = (const float*)d_in[4];
    const float* wa1 = (const float*)d_in[5];
    const float* ba1 = (const float*)d_in[6];
    const float* wa2 = (const float*)d_in[7];
    const float* ba2 = (const float*)d_in[8];
    const int*   ei  = (const int*)d_in[9];   // int32 edge_index [2, E]
    float* out = (float*)d_out;

    int N = in_sizes[0] / D;
    int E = in_sizes[9] / 2;
    int tiles = (N + 127) / 128;
    int nb = (N + 255) / 256;

    const int gemm_smem = (384 * XPAD) * (int)sizeof(uint32_t)
                        + (128 * 4 * 2 + 128) * (int)sizeof(float);   // ~207 KB
    cudaFuncSetAttribute(gat_gemm_kernel,
                         cudaFuncAttributeMaxDynamicSharedMemorySize, gemm_smem);

    // Launch order steers ncu (captures 4th launch) onto the GEMM.
    convert_kernel<<<1024, 256>>>(X, W1, W2, N);             // 1
    hist_kernel<<<(E + 255) / 256, 256>>>(ei, E, N);         // 2
    scan1_kernel<<<nb, 256>>>(N);                            // 3
    int gblocks = tiles < 148 ? tiles : 148;
    gat_gemm_kernel<<<gblocks, 512, gemm_smem>>>(            // 4  <- profiled
        b1, b2, wa1, ba1, wa2, ba2, out, N, tiles);
    scanB_kernel<<<nb, 256>>>(nb, N);                        // 5
    fill_kernel<<<(E + 255) / 256, 256>>>(ei, E, N);         // 6
    gat_gather_kernel<<<(N * 32 + 255) / 256, 256>>>(out, N);// 7
}